// round 7
// baseline (speedup 1.0000x reference)
#include <cuda_runtime.h>
#include <cstdint>

// ---------------------------------------------------------------------------
// Problem constants
// ---------------------------------------------------------------------------
#define NEURONS  512
#define CHANNELS 384
#define HWSZ     169
#define BATCH    512
#define K_TOTAL  (CHANNELS * HWSZ)      // 64896

// k-tiles of 32 floats
#define BM 128
#define BN 128
#define BKF 32
#define TILES_TOTAL (K_TOTAL / BKF)     // 2028

// Hybrid split: tensor CTAs take tiles [0, T_TENS), FFMA CTAs the rest.
#define T_TENS 1644                      // 81% of K on tensor pipe
#define T_FFMA (TILES_TOTAL - T_TENS)    // 384 on fp32 FMA pipe
#define SPLITS_T 9
#define SPLITS_F 9
#define N_POS 16                         // 4x4 (m,n) tile positions
#define CTAS_T (N_POS * SPLITS_T)        // 144
#define SPLITS (SPLITS_T + SPLITS_F)     // 18 partial slots

#define STAGES 3
#define A_BYTES (BM * 128)               // 16 KB
#define B_BYTES (BN * 128)               // 16 KB
#define STAGE_BYTES (A_BYTES + B_BYTES)  // 32 KB
#define SMEM_TOTAL (STAGES * STAGE_BYTES)// 96 KB (uniform for both roles)

// Scratch (__device__ globals per allocation rules)
__device__ float g_W[(size_t)NEURONS * K_TOTAL];     // [n][k], tf32 values
__device__ float g_part[SPLITS][BATCH * NEURONS];    // split-K partials

// ---------------------------------------------------------------------------
// Helpers (baseline PTX only: sm_80-class)
// ---------------------------------------------------------------------------
__device__ __forceinline__ uint32_t s2u(const void* p) {
    return (uint32_t)__cvta_generic_to_shared(p);
}

// 32B-granular swizzle for the tensor-role tiles
__device__ __forceinline__ uint32_t tile_off(uint32_t row, uint32_t c16) {
    return row * 128u + ((((c16 >> 1) ^ (row & 3u)) << 5)) + ((c16 & 1u) << 4);
}

#define CPA16(dst, src) \
    asm volatile("cp.async.cg.shared.global [%0], [%1], 16;" :: "r"(dst), "l"(src))
#define CP_COMMIT()  asm volatile("cp.async.commit_group;" ::: "memory")
#define CP_WAIT(n)   asm volatile("cp.async.wait_group %0;" :: "n"(n) : "memory")

#define LDSM_X4(r0, r1, r2, r3, a) \
    asm volatile("ldmatrix.sync.aligned.m8n8.x4.shared.b16 {%0,%1,%2,%3}, [%4];" \
                 : "=r"(r0), "=r"(r1), "=r"(r2), "=r"(r3) : "r"(a))

#define MMA_TF32(c, a, b0, b1) \
    asm volatile("mma.sync.aligned.m16n8k8.row.col.f32.tf32.tf32.f32 " \
                 "{%0,%1,%2,%3},{%4,%5,%6,%7},{%8,%9},{%0,%1,%2,%3};" \
                 : "+f"((c)[0]), "+f"((c)[1]), "+f"((c)[2]), "+f"((c)[3]) \
                 : "r"((a)[0]), "r"((a)[1]), "r"((a)[2]), "r"((a)[3]), \
                   "r"(b0), "r"(b1))

#define FMA2(d, a, b) asm("fma.rn.f32x2 %0, %1, %2, %0;" : "+l"(d) : "l"(a), "l"(b))
#define PACK2(o, x)   asm("mov.b64 %0, {%1, %1};" : "=l"(o) : "r"(x))

__device__ __forceinline__ uint32_t cvt_rna_tf32(uint32_t x) {
    uint32_t r;
    asm("cvt.rna.tf32.f32 %0, %1;" : "=r"(r) : "f"(__uint_as_float(x)));
    return r;
}

// ---------------------------------------------------------------------------
// Kernel 1: g_W[n][k] = rna_tf32(W_d[n,c] * W_s[n,hw]); one block per neuron,
// float4 stores (was issue-bound at scalar).
// ---------------------------------------------------------------------------
__global__ void __launch_bounds__(256) precompute_w(const float* __restrict__ W_s,
                                                    const float* __restrict__ W_d) {
    const int n = blockIdx.x;
    __shared__ float ws[HWSZ];
    __shared__ float wd[CHANNELS];
    for (int i = threadIdx.x; i < HWSZ; i += 256)     ws[i] = W_s[n * HWSZ + i];
    for (int i = threadIdx.x; i < CHANNELS; i += 256) wd[i] = W_d[n * CHANNELS + i];
    __syncthreads();
    float4* dst4 = (float4*)(g_W + (size_t)n * K_TOTAL);
    for (int q = threadIdx.x; q < K_TOTAL / 4; q += 256) {
        int k = q * 4;
        float v[4];
        #pragma unroll
        for (int i = 0; i < 4; i++) {
            int ki = k + i;
            int c  = ki / HWSZ;            // constant divisor -> mul-hi
            int hw = ki - c * HWSZ;
            float t = wd[c] * ws[hw];
            uint32_t u;
            asm("cvt.rna.tf32.f32 %0, %1;" : "=r"(u) : "f"(t));
            v[i] = __uint_as_float(u);
        }
        dst4[q] = make_float4(v[0], v[1], v[2], v[3]);
    }
}

// ---------------------------------------------------------------------------
// Kernel 2: hybrid GEMM. bid < 144: tf32 mma.sync role. bid >= 144: FFMA2 role.
// Both roles: CTA tile 128x128, 256 threads. Uniform 96KB smem -> 2 CTAs/SM,
// classic placement pairs (bid, bid+148) on one SM => tensor+ffma share pipes.
// ---------------------------------------------------------------------------
__global__ void __launch_bounds__(256, 2) gemm_hybrid(const float* __restrict__ x) {
    extern __shared__ char smem[];
    const uint32_t sbase = s2u(smem);

    const int bid  = blockIdx.x;
    const int tid  = threadIdx.x;
    const int wid  = tid >> 5;
    const int lane = tid & 31;

    const bool is_tensor = (bid < CTAS_T);
    const int idx = is_tensor ? bid : bid - CTAS_T;
    const int s   = idx / N_POS;
    const int pos = idx - s * N_POS;
    const int n0  = (pos & 3) * BN;
    const int m0  = (pos >> 2) * BM;

    if (is_tensor) {
        // ================= tensor role: tiles [0, T_TENS) ====================
        const int NT  = 182 + (s < 6 ? 1 : 0);          // 6x183 + 3x182 = 1644
        const int ks0 = 182 * s + (s < 6 ? s : 6);

        const float* xbase = x   + (size_t)m0 * K_TOTAL + (size_t)ks0 * BKF;
        const float* wbase = g_W + (size_t)n0 * K_TOTAL + (size_t)ks0 * BKF;

        const int wm = (wid & 1) * 64;
        const int wn = (wid >> 1) * 32;
        const int sub = lane >> 3;
        const int r8  = lane & 7;

        float acc[4][4][4];
        #pragma unroll
        for (int i = 0; i < 4; i++)
            #pragma unroll
            for (int j = 0; j < 4; j++)
                #pragma unroll
                for (int f = 0; f < 4; f++) acc[i][j][f] = 0.f;

        auto fill = [&](int t) {
            const uint32_t sa = sbase + (t % STAGES) * STAGE_BYTES;
            const uint32_t sB = sa + A_BYTES;
            const float* xs = xbase + (size_t)t * BKF;
            const float* wsr = wbase + (size_t)t * BKF;
            #pragma unroll
            for (int i = 0; i < 4; i++) {
                int slot = tid + i * 256;
                uint32_t row = slot >> 3, c = slot & 7;
                uint32_t off = tile_off(row, c);
                CPA16(sa + off, xs + (size_t)row * K_TOTAL + c * 4);
                CPA16(sB + off, wsr + (size_t)row * K_TOTAL + c * 4);
            }
            CP_COMMIT();
        };

        fill(0);
        fill(1);

        for (int t = 0; t < NT; t++) {
            CP_WAIT(1);
            __syncthreads();
            if (t + 2 < NT) fill(t + 2);

            const uint32_t sa = sbase + (t % STAGES) * STAGE_BYTES;
            const uint32_t sB = sa + A_BYTES;

            #pragma unroll
            for (int ks = 0; ks < 4; ks++) {
                uint32_t a[4][4];
                #pragma unroll
                for (int i = 0; i < 4; i++) {
                    uint32_t row = wm + i * 16 + (sub & 1) * 8 + r8;
                    uint32_t addr = sa + row * 128 +
                                    (((uint32_t)ks ^ (row & 3u)) << 5) + ((sub >> 1) << 4);
                    LDSM_X4(a[i][0], a[i][1], a[i][2], a[i][3], addr);
                    a[i][0] = cvt_rna_tf32(a[i][0]);
                    a[i][1] = cvt_rna_tf32(a[i][1]);
                    a[i][2] = cvt_rna_tf32(a[i][2]);
                    a[i][3] = cvt_rna_tf32(a[i][3]);
                }
                uint32_t b[2][4];
                #pragma unroll
                for (int p = 0; p < 2; p++) {
                    uint32_t row = wn + p * 16 + (sub >> 1) * 8 + r8;
                    uint32_t addr = sB + row * 128 +
                                    (((uint32_t)ks ^ (row & 3u)) << 5) + ((sub & 1) << 4);
                    LDSM_X4(b[p][0], b[p][1], b[p][2], b[p][3], addr);
                }
                #pragma unroll
                for (int i = 0; i < 4; i++)
                    #pragma unroll
                    for (int j = 0; j < 4; j++)
                        MMA_TF32(acc[i][j], a[i], b[j >> 1][(j & 1) * 2],
                                 b[j >> 1][(j & 1) * 2 + 1]);
            }
            __syncthreads();
        }

        const int g  = lane >> 2;
        const int t4 = lane & 3;
        float* base = g_part[s];
        #pragma unroll
        for (int i = 0; i < 4; i++) {
            #pragma unroll
            for (int j = 0; j < 4; j++) {
                int row = m0 + wm + i * 16 + g;
                int col = n0 + wn + j * 8 + t4 * 2;
                *(float2*)&base[(size_t)row * NEURONS + col] =
                    make_float2(acc[i][j][0], acc[i][j][1]);
                *(float2*)&base[(size_t)(row + 8) * NEURONS + col] =
                    make_float2(acc[i][j][2], acc[i][j][3]);
            }
        }
    } else {
        // ================= FFMA role: tiles [T_TENS, 2028) ===================
        const int NTf = 42 + (s < 6 ? 1 : 0);           // 6x43 + 3x42 = 384
        const int kt0 = T_TENS + 42 * s + (s < 6 ? s : 6);
        const int k0f = kt0 * BKF;
        const int NSTEPS = NTf * 4;                     // BK = 8 floats per step

        float (*As)[BM] = (float(*)[BM])smem;           // [8][128]
        float (*Bs)[BN] = (float(*)[BN])(smem + 8 * BM * 4);

        const int a_row = tid >> 1;
        const int a_kc  = (tid & 1) * 4;
        const float* a_ptr = x + (size_t)(m0 + a_row) * K_TOTAL + k0f + a_kc;

        const int b_col = tid >> 1;
        const int b_kc  = (tid & 1) * 4;
        const float* b_ptr = g_W + (size_t)(n0 + b_col) * K_TOTAL + k0f + b_kc;

        const int tx = tid & 15;
        const int ty = tid >> 4;

        uint64_t acc[8][4];
        #pragma unroll
        for (int i = 0; i < 8; i++)
            #pragma unroll
            for (int j = 0; j < 4; j++) acc[i][j] = 0ull;

        float4 a_reg = *(const float4*)a_ptr;
        float4 b_reg = *(const float4*)b_ptr;

        for (int step = 0; step < NSTEPS; ++step) {
            As[a_kc + 0][a_row] = a_reg.x;
            As[a_kc + 1][a_row] = a_reg.y;
            As[a_kc + 2][a_row] = a_reg.z;
            As[a_kc + 3][a_row] = a_reg.w;
            Bs[b_kc + 0][b_col] = b_reg.x;
            Bs[b_kc + 1][b_col] = b_reg.y;
            Bs[b_kc + 2][b_col] = b_reg.z;
            Bs[b_kc + 3][b_col] = b_reg.w;
            __syncthreads();

            if (step + 1 < NSTEPS) {
                a_ptr += 8;
                b_ptr += 8;
                a_reg = *(const float4*)a_ptr;
                b_reg = *(const float4*)b_ptr;
            }

            #pragma unroll
            for (int kk = 0; kk < 8; ++kk) {
                float4 a0 = *(const float4*)&As[kk][ty * 8];
                float4 a1 = *(const float4*)&As[kk][ty * 8 + 4];
                ulonglong2 bq0 = *(const ulonglong2*)&Bs[kk][tx * 8];
                ulonglong2 bq1 = *(const ulonglong2*)&Bs[kk][tx * 8 + 4];
                uint64_t bp[4] = {bq0.x, bq0.y, bq1.x, bq1.y};
                float av[8] = {a0.x, a0.y, a0.z, a0.w, a1.x, a1.y, a1.z, a1.w};
                #pragma unroll
                for (int i = 0; i < 8; i++) {
                    uint64_t a2;
                    PACK2(a2, __float_as_uint(av[i]));
                    #pragma unroll
                    for (int j = 0; j < 4; j++) FMA2(acc[i][j], a2, bp[j]);
                }
            }
            __syncthreads();
        }

        float* dst = g_part[SPLITS_T + s] +
                     (size_t)(m0 + ty * 8) * NEURONS + n0 + tx * 8;
        #pragma unroll
        for (int i = 0; i < 8; i++) {
            *(ulonglong2*)(dst + (size_t)i * NEURONS)     = make_ulonglong2(acc[i][0], acc[i][1]);
            *(ulonglong2*)(dst + (size_t)i * NEURONS + 4) = make_ulonglong2(acc[i][2], acc[i][3]);
        }
    }
}

// ---------------------------------------------------------------------------
// Kernel 3: sum split-K partials + bias (float4)
// ---------------------------------------------------------------------------
__global__ void __launch_bounds__(256) reduce_out(const float* __restrict__ W_b,
                                                  float* __restrict__ out) {
    int i4 = blockIdx.x * blockDim.x + threadIdx.x;
    int n4 = i4 & (NEURONS / 4 - 1);
    float4 a = ((const float4*)W_b)[n4];
    #pragma unroll
    for (int sp = 0; sp < SPLITS; sp++) {
        float4 p = *(const float4*)&g_part[sp][(size_t)i4 * 4];
        a.x += p.x; a.y += p.y; a.z += p.z; a.w += p.w;
    }
    ((float4*)out)[i4] = a;
}

// ---------------------------------------------------------------------------
// Entry point
// ---------------------------------------------------------------------------
extern "C" void kernel_launch(void* const* d_in, const int* in_sizes, int n_in,
                              void* d_out, int out_size) {
    const float* x   = (const float*)d_in[0];   // [512, 384, 13, 13]
    const float* W_s = (const float*)d_in[1];   // [512, 13, 13]
    const float* W_d = (const float*)d_in[2];   // [512, 384]
    const float* W_b = (const float*)d_in[3];   // [1, 512]
    float* out = (float*)d_out;                 // [512, 512]

    (void)cudaFuncSetAttribute(gemm_hybrid,
        cudaFuncAttributeMaxDynamicSharedMemorySize, SMEM_TOTAL);

    precompute_w<<<NEURONS, 256>>>(W_s, W_d);

    gemm_hybrid<<<2 * CTAS_T, 256, SMEM_TOTAL>>>(x);   // 288 CTAs, 1D

    reduce_out<<<(BATCH * NEURONS) / (256 * 4), 256>>>(W_b, out);
}

// round 8
// speedup vs baseline: 1.5188x; 1.5188x over previous
#include <cuda_runtime.h>
#include <cstdint>

// ---------------------------------------------------------------------------
// Problem constants
// ---------------------------------------------------------------------------
#define NEURONS  512
#define CHANNELS 384
#define HWSZ     169
#define BATCH    512
#define K_TOTAL  (CHANNELS * HWSZ)      // 64896

// GEMM tiling: out[512,512] = x[512,K] @ W^T,  W[n,k] = W_d[n,c]*W_s[n,hw]
#define BM 128
#define BN 128
#define BKF 32                           // k floats per tile (128 B row)
#define SPLITS 18                        // uneven: 12 splits of 113, 6 of 112
#define STAGES 3

#define A_BYTES (BM * 128)               // 16 KB
#define B_BYTES (BN * 128)               // 16 KB
#define STAGE_BYTES (A_BYTES + B_BYTES)  // 32 KB
#define SMEM_TOTAL (STAGES * STAGE_BYTES)// 96 KB

// Scratch (__device__ globals per allocation rules)
__device__ float g_W[(size_t)NEURONS * K_TOTAL];     // [n][k]
__device__ float g_part[SPLITS][BATCH * NEURONS];    // split-K partials

// ---------------------------------------------------------------------------
// Helpers (baseline PTX: sm_80-class only; compute_103 target has no 'a' isa)
// ---------------------------------------------------------------------------
__device__ __forceinline__ uint32_t s2u(const void* p) {
    return (uint32_t)__cvta_generic_to_shared(p);
}

// 32B-granular swizzle: 16B chunk c (0..7) of row r
__device__ __forceinline__ uint32_t tile_off(uint32_t row, uint32_t c16) {
    return row * 128u + ((((c16 >> 1) ^ (row & 3u)) << 5)) + ((c16 & 1u) << 4);
}

#define CPA16(dst, src) \
    asm volatile("cp.async.cg.shared.global [%0], [%1], 16;" :: "r"(dst), "l"(src))
#define CP_COMMIT()  asm volatile("cp.async.commit_group;" ::: "memory")
#define CP_WAIT(n)   asm volatile("cp.async.wait_group %0;" :: "n"(n) : "memory")

#define LDSM_X4(r0, r1, r2, r3, a) \
    asm volatile("ldmatrix.sync.aligned.m8n8.x4.shared.b16 {%0,%1,%2,%3}, [%4];" \
                 : "=r"(r0), "=r"(r1), "=r"(r2), "=r"(r3) : "r"(a))

// fp16 MMA: m16n8k16, f32 accum
#define MMA_F16(c, a, b) \
    asm volatile("mma.sync.aligned.m16n8k16.row.col.f32.f16.f16.f32 " \
                 "{%0,%1,%2,%3},{%4,%5,%6,%7},{%8,%9},{%0,%1,%2,%3};" \
                 : "+f"((c)[0]), "+f"((c)[1]), "+f"((c)[2]), "+f"((c)[3]) \
                 : "r"((a)[0]), "r"((a)[1]), "r"((a)[2]), "r"((a)[3]), \
                   "r"((b)[0]), "r"((b)[1]))

// pack two fp32 (bit images) into one f16x2 reg: {hi, lo}
__device__ __forceinline__ uint32_t pack_f16(uint32_t hi, uint32_t lo) {
    uint32_t d;
    asm("cvt.rn.f16x2.f32 %0, %1, %2;" : "=r"(d)
        : "f"(__uint_as_float(hi)), "f"(__uint_as_float(lo)));
    return d;
}

// ---------------------------------------------------------------------------
// Kernel 1: g_W[n][k] = W_d[n,c] * W_s[n,hw]; 4 blocks per neuron for occupancy
// ---------------------------------------------------------------------------
__global__ void __launch_bounds__(256) precompute_w(const float* __restrict__ W_s,
                                                    const float* __restrict__ W_d) {
    const int n = blockIdx.x;
    const int q = blockIdx.y;                 // quarter of k-range
    __shared__ float ws[HWSZ];
    __shared__ float wd[CHANNELS];
    for (int i = threadIdx.x; i < HWSZ; i += 256)     ws[i] = W_s[n * HWSZ + i];
    for (int i = threadIdx.x; i < CHANNELS; i += 256) wd[i] = W_d[n * CHANNELS + i];
    __syncthreads();
    const int QK = K_TOTAL / 4;               // 16224, divisible by 4
    float4* dst4 = (float4*)(g_W + (size_t)n * K_TOTAL + (size_t)q * QK);
    const int kbase = q * QK;
    for (int v = threadIdx.x; v < QK / 4; v += 256) {
        int k = kbase + v * 4;
        float r[4];
        #pragma unroll
        for (int i = 0; i < 4; i++) {
            int ki = k + i;
            int c  = ki / HWSZ;                // constant divisor -> mul-hi
            int hw = ki - c * HWSZ;
            r[i] = wd[c] * ws[hw];
        }
        dst4[v] = make_float4(r[0], r[1], r[2], r[3]);
    }
}

// ---------------------------------------------------------------------------
// Kernel 2: fp16 mma.sync split-K GEMM. R6 pipeline verbatim (fp32 smem tiles,
// same swizzle/ldmatrix); fragments packed fp32->f16x2 in-register with a
// k-permutation applied identically to A and B (dot product invariant).
// ---------------------------------------------------------------------------
__global__ void __launch_bounds__(256, 2) gemm_f16(const float* __restrict__ x) {
    extern __shared__ char smem[];
    const uint32_t sbase = s2u(smem);

    const int tid  = threadIdx.x;
    const int wid  = tid >> 5;
    const int lane = tid & 31;
    const int n0 = blockIdx.x * BN;
    const int m0 = blockIdx.y * BM;
    const int s  = blockIdx.z;

    // uneven split-K: first 12 splits get 113 k-steps, rest 112
    const int NT    = 112 + (s < 12 ? 1 : 0);
    const int kstrt = 112 * s + (s < 12 ? s : 12);

    const float* xbase = x   + (size_t)m0 * K_TOTAL + (size_t)kstrt * BKF;
    const float* wbase = g_W + (size_t)n0 * K_TOTAL + (size_t)kstrt * BKF;

    const int wm = (wid & 1) * 64;
    const int wn = (wid >> 1) * 32;
    const int sub = lane >> 3;
    const int r8  = lane & 7;

    float acc[4][4][4];
    #pragma unroll
    for (int i = 0; i < 4; i++)
        #pragma unroll
        for (int j = 0; j < 4; j++)
            #pragma unroll
            for (int f = 0; f < 4; f++) acc[i][j][f] = 0.f;

    auto fill = [&](int t) {
        const uint32_t sa = sbase + (t % STAGES) * STAGE_BYTES;
        const uint32_t sB = sa + A_BYTES;
        const float* xs = xbase + (size_t)t * BKF;
        const float* wr = wbase + (size_t)t * BKF;
        #pragma unroll
        for (int i = 0; i < 4; i++) {
            int slot = tid + i * 256;
            uint32_t row = slot >> 3, c = slot & 7;
            uint32_t off = tile_off(row, c);
            CPA16(sa + off, xs + (size_t)row * K_TOTAL + c * 4);
            CPA16(sB + off, wr + (size_t)row * K_TOTAL + c * 4);
        }
        CP_COMMIT();
    };

    fill(0);
    fill(1);

    for (int t = 0; t < NT; t++) {
        CP_WAIT(1);
        __syncthreads();
        if (t + 2 < NT) fill(t + 2);

        const uint32_t sa = sbase + (t % STAGES) * STAGE_BYTES;
        const uint32_t sB = sa + A_BYTES;

        #pragma unroll
        for (int kh = 0; kh < 2; kh++) {          // two k16 halves of the k32 tile
            const uint32_t c0 = kh * 2;           // 32B chunk indices c0, c0+1
            // ---- A fragments: 4 m16 tiles -> fp16 m16n8k16 A frags ----------
            uint32_t ah[4][4];
            #pragma unroll
            for (int i = 0; i < 4; i++) {
                uint32_t row  = wm + i * 16 + (sub & 1) * 8 + r8;
                uint32_t base = sa + row * 128 + ((sub >> 1) << 4);
                uint32_t t0[4], t1[4];
                LDSM_X4(t0[0], t0[1], t0[2], t0[3],
                        base + ((c0 ^ (row & 3u)) << 5));
                LDSM_X4(t1[0], t1[1], t1[2], t1[3],
                        base + (((c0 + 1) ^ (row & 3u)) << 5));
                // permuted pair (lo=k, hi=k+4); rows / rows+8 / second k8 group
                ah[i][0] = pack_f16(t0[2], t0[0]);
                ah[i][1] = pack_f16(t0[3], t0[1]);
                ah[i][2] = pack_f16(t1[2], t1[0]);
                ah[i][3] = pack_f16(t1[3], t1[1]);
            }
            // ---- B fragments: 4 n8 tiles -> fp16 B frags --------------------
            uint32_t bh[4][2];
            #pragma unroll
            for (int p = 0; p < 2; p++) {
                uint32_t row  = wn + p * 16 + (sub >> 1) * 8 + r8;
                uint32_t base = sB + row * 128 + ((sub & 1) << 4);
                uint32_t t0[4], t1[4];
                LDSM_X4(t0[0], t0[1], t0[2], t0[3],
                        base + ((c0 ^ (row & 3u)) << 5));
                LDSM_X4(t1[0], t1[1], t1[2], t1[3],
                        base + (((c0 + 1) ^ (row & 3u)) << 5));
                bh[p * 2 + 0][0] = pack_f16(t0[1], t0[0]);   // n group, ks even
                bh[p * 2 + 0][1] = pack_f16(t1[1], t1[0]);   // n group, ks odd
                bh[p * 2 + 1][0] = pack_f16(t0[3], t0[2]);   // n+8 group
                bh[p * 2 + 1][1] = pack_f16(t1[3], t1[2]);
            }
            #pragma unroll
            for (int i = 0; i < 4; i++)
                #pragma unroll
                for (int j = 0; j < 4; j++)
                    MMA_F16(acc[i][j], ah[i], bh[j]);
        }
        __syncthreads();
    }

    // ---- epilogue: write split partial tile ---------------------------------
    const int g  = lane >> 2;
    const int t4 = lane & 3;
    float* base = g_part[s];
    #pragma unroll
    for (int i = 0; i < 4; i++) {
        #pragma unroll
        for (int j = 0; j < 4; j++) {
            int row = m0 + wm + i * 16 + g;
            int col = n0 + wn + j * 8 + t4 * 2;
            *(float2*)&base[(size_t)row * NEURONS + col] =
                make_float2(acc[i][j][0], acc[i][j][1]);
            *(float2*)&base[(size_t)(row + 8) * NEURONS + col] =
                make_float2(acc[i][j][2], acc[i][j][3]);
        }
    }
}

// ---------------------------------------------------------------------------
// Kernel 3: sum split-K partials + bias (float4)
// ---------------------------------------------------------------------------
__global__ void __launch_bounds__(256) reduce_out(const float* __restrict__ W_b,
                                                  float* __restrict__ out) {
    int i4 = blockIdx.x * blockDim.x + threadIdx.x;
    int n4 = i4 & (NEURONS / 4 - 1);
    float4 a = ((const float4*)W_b)[n4];
    #pragma unroll
    for (int sp = 0; sp < SPLITS; sp++) {
        float4 p = *(const float4*)&g_part[sp][(size_t)i4 * 4];
        a.x += p.x; a.y += p.y; a.z += p.z; a.w += p.w;
    }
    ((float4*)out)[i4] = a;
}

// ---------------------------------------------------------------------------
// Entry point
// ---------------------------------------------------------------------------
extern "C" void kernel_launch(void* const* d_in, const int* in_sizes, int n_in,
                              void* d_out, int out_size) {
    const float* x   = (const float*)d_in[0];   // [512, 384, 13, 13]
    const float* W_s = (const float*)d_in[1];   // [512, 13, 13]
    const float* W_d = (const float*)d_in[2];   // [512, 384]
    const float* W_b = (const float*)d_in[3];   // [1, 512]
    float* out = (float*)d_out;                 // [512, 512]

    (void)cudaFuncSetAttribute(gemm_f16,
        cudaFuncAttributeMaxDynamicSharedMemorySize, SMEM_TOTAL);

    dim3 pre_grid(NEURONS, 4);
    precompute_w<<<pre_grid, 256>>>(W_s, W_d);

    dim3 grid(NEURONS / BN, BATCH / BM, SPLITS);   // 4 x 4 x 18 = 288 CTAs
    gemm_f16<<<grid, 256, SMEM_TOTAL>>>(x);

    reduce_out<<<(BATCH * NEURONS) / (256 * 4), 256>>>(W_b, out);
}

// round 10
// speedup vs baseline: 2.4746x; 1.6293x over previous
#include <cuda_runtime.h>
#include <cuda_fp16.h>
#include <cstdint>

// ---------------------------------------------------------------------------
// Problem constants
// ---------------------------------------------------------------------------
#define NEURONS  512
#define CHANNELS 384
#define HWSZ     169
#define BATCH    512
#define K_TOTAL  (CHANNELS * HWSZ)      // 64896

// GEMM tiling: out[512,512] = x[512,K] @ W^T,  W[n,k] = W_d[n,c]*W_s[n,hw]
// fp16 operands in smem, fp32 accumulate. k-tile = 64 halves (128 B row).
#define BM 128
#define BN 128
#define KH 64                            // halves per k-tile (128 B)
#define TILES64 (K_TOTAL / KH)           // 1014
#define SPLITS 18                        // 6 splits of 57 tiles + 12 of 56
#define STAGES 3

#define A_BYTES (BM * 128)               // 16 KB (fp16)
#define B_BYTES (BN * 128)               // 16 KB
#define STAGE_BYTES (A_BYTES + B_BYTES)  // 32 KB
#define SMEM_TOTAL (STAGES * STAGE_BYTES)// 96 KB

// Scratch (__device__ globals per allocation rules)
__device__ __half g_x[(size_t)BATCH * K_TOTAL];      // x converted to fp16
__device__ __half g_w[(size_t)NEURONS * K_TOTAL];    // rank-1 weights, fp16
__device__ float  g_part[SPLITS][BATCH * NEURONS];   // split-K partials

// ---------------------------------------------------------------------------
// Helpers (baseline PTX: sm_80-class; compute_103 target has no 'a' isa)
// ---------------------------------------------------------------------------
__device__ __forceinline__ uint32_t s2u(const void* p) {
    return (uint32_t)__cvta_generic_to_shared(p);
}

// Full SW128 swizzle: 16B chunk c (0..7) of 128B row r -> conflict-free for
// both cp.async row fills and ldmatrix 8x8 column reads.
__device__ __forceinline__ uint32_t sw_off(uint32_t row, uint32_t c16) {
    return row * 128u + ((c16 ^ (row & 7u)) << 4);
}

// pack two fp32 into one f16x2 reg: {hi, lo}
__device__ __forceinline__ uint32_t pack_f16(float hi, float lo) {
    uint32_t d;
    asm("cvt.rn.f16x2.f32 %0, %1, %2;" : "=r"(d) : "f"(hi), "f"(lo));
    return d;
}

#define CPA16(dst, src) \
    asm volatile("cp.async.cg.shared.global [%0], [%1], 16;" :: "r"(dst), "l"(src))
#define CP_COMMIT()  asm volatile("cp.async.commit_group;" ::: "memory")
#define CP_WAIT(n)   asm volatile("cp.async.wait_group %0;" :: "n"(n) : "memory")

#define LDSM_X4(r0, r1, r2, r3, a) \
    asm volatile("ldmatrix.sync.aligned.m8n8.x4.shared.b16 {%0,%1,%2,%3}, [%4];" \
                 : "=r"(r0), "=r"(r1), "=r"(r2), "=r"(r3) : "r"(a))

// fp16 MMA: m16n8k16, f32 accum
#define MMA_F16(c, a, b) \
    asm volatile("mma.sync.aligned.m16n8k16.row.col.f32.f16.f16.f32 " \
                 "{%0,%1,%2,%3},{%4,%5,%6,%7},{%8,%9},{%0,%1,%2,%3};" \
                 : "+f"((c)[0]), "+f"((c)[1]), "+f"((c)[2]), "+f"((c)[3]) \
                 : "r"((a)[0]), "r"((a)[1]), "r"((a)[2]), "r"((a)[3]), \
                   "r"((b)[0]), "r"((b)[1]))

// ---------------------------------------------------------------------------
// Kernel 0: convert x (fp32) -> g_x (fp16). 8 floats -> 16B store per iter.
// ---------------------------------------------------------------------------
__global__ void __launch_bounds__(256) convert_x(const float* __restrict__ x) {
    const size_t idx = (size_t)blockIdx.x * 256 + threadIdx.x;  // 8-elem slots
    const float4* src = (const float4*)x + idx * 2;
    float4 v0 = src[0];
    float4 v1 = src[1];
    uint4 o;
    o.x = pack_f16(v0.y, v0.x);
    o.y = pack_f16(v0.w, v0.z);
    o.z = pack_f16(v1.y, v1.x);
    o.w = pack_f16(v1.w, v1.z);
    ((uint4*)g_x)[idx] = o;
}

// ---------------------------------------------------------------------------
// Kernel 1: g_w[n][k] = fp16(W_d[n,c] * W_s[n,hw]); grid (512, 4)
// ---------------------------------------------------------------------------
__global__ void __launch_bounds__(256) precompute_w(const float* __restrict__ W_s,
                                                    const float* __restrict__ W_d) {
    const int n = blockIdx.x;
    const int q = blockIdx.y;
    __shared__ float ws[HWSZ];
    __shared__ float wd[CHANNELS];
    for (int i = threadIdx.x; i < HWSZ; i += 256)     ws[i] = W_s[n * HWSZ + i];
    for (int i = threadIdx.x; i < CHANNELS; i += 256) wd[i] = W_d[n * CHANNELS + i];
    __syncthreads();
    const int QK = K_TOTAL / 4;                       // 16224
    const int kbase = q * QK;
    uint4* dst = (uint4*)(g_w + (size_t)n * K_TOTAL + kbase);
    for (int v = threadIdx.x; v < QK / 8; v += 256) {
        int k = kbase + v * 8;
        float r[8];
        #pragma unroll
        for (int i = 0; i < 8; i++) {
            int ki = k + i;
            int c  = ki / HWSZ;                       // constant divisor -> mul-hi
            int hw = ki - c * HWSZ;
            r[i] = wd[c] * ws[hw];
        }
        uint4 o;
        o.x = pack_f16(r[1], r[0]);
        o.y = pack_f16(r[3], r[2]);
        o.z = pack_f16(r[5], r[4]);
        o.w = pack_f16(r[7], r[6]);
        dst[v] = o;
    }
}

// ---------------------------------------------------------------------------
// Kernel 2: fp16 mma.sync split-K GEMM, fp16 smem tiles, true SW128 swizzle.
// 256 threads = 8 warps, warp tile 64x32, CTA tile 128x128xk64.
// ---------------------------------------------------------------------------
__global__ void __launch_bounds__(256, 2) gemm_f16(void) {
    extern __shared__ char smem[];
    const uint32_t sbase = s2u(smem);

    const int tid  = threadIdx.x;
    const int wid  = tid >> 5;
    const int lane = tid & 31;
    const int n0 = blockIdx.x * BN;
    const int m0 = blockIdx.y * BM;
    const int s  = blockIdx.z;

    // uneven split-K over 1014 k64-tiles: first 6 splits get 57, rest 56
    const int NT  = 56 + (s < 6 ? 1 : 0);
    const int ts0 = 56 * s + (s < 6 ? s : 6);

    const __half* xbase = g_x + (size_t)m0 * K_TOTAL + (size_t)ts0 * KH;
    const __half* wbase = g_w + (size_t)n0 * K_TOTAL + (size_t)ts0 * KH;

    const int wm = (wid & 1) * 64;
    const int wn = (wid >> 1) * 32;
    const int sub = lane >> 3;            // 0..3
    const int r8  = lane & 7;

    float acc[4][4][4];
    #pragma unroll
    for (int i = 0; i < 4; i++)
        #pragma unroll
        for (int j = 0; j < 4; j++)
            #pragma unroll
            for (int f = 0; f < 4; f++) acc[i][j][f] = 0.f;

    // stage fill: A 1024 chunks + B 1024 chunks of 16 B; 8 per thread
    auto fill = [&](int t) {
        const uint32_t sa = sbase + (t % STAGES) * STAGE_BYTES;
        const uint32_t sB = sa + A_BYTES;
        const __half* xs = xbase + (size_t)t * KH;
        const __half* wr = wbase + (size_t)t * KH;
        #pragma unroll
        for (int i = 0; i < 4; i++) {
            int slot = tid + i * 256;            // 0..1023
            uint32_t row = slot >> 3, c = slot & 7;
            uint32_t off = sw_off(row, c);
            CPA16(sa + off, xs + (size_t)row * K_TOTAL + c * 8);
            CPA16(sB + off, wr + (size_t)row * K_TOTAL + c * 8);
        }
        CP_COMMIT();
    };

    fill(0);
    fill(1);

    for (int t = 0; t < NT; t++) {
        CP_WAIT(1);
        __syncthreads();
        if (t + 2 < NT) fill(t + 2);

        const uint32_t sa = sbase + (t % STAGES) * STAGE_BYTES;
        const uint32_t sB = sa + A_BYTES;

        #pragma unroll
        for (int ks = 0; ks < 4; ks++) {         // four k16 steps per k64 tile
            // A: 4 m16k16 fragments. matrices: (m-half=sub&1, k-chunk=sub>>1)
            uint32_t a[4][4];
            #pragma unroll
            for (int i = 0; i < 4; i++) {
                uint32_t row   = wm + i * 16 + (sub & 1) * 8 + r8;
                uint32_t chunk = ks * 2 + (sub >> 1);
                LDSM_X4(a[i][0], a[i][1], a[i][2], a[i][3],
                        sa + sw_off(row, chunk));
            }
            // B: 4 n8k16 fragments via 2 LDSM.x4. matrices: (n-half=sub>>1, k-chunk=sub&1)
            uint32_t b[4][2];
            #pragma unroll
            for (int p = 0; p < 2; p++) {
                uint32_t row   = wn + p * 16 + (sub >> 1) * 8 + r8;
                uint32_t chunk = ks * 2 + (sub & 1);
                uint32_t t0, t1, t2, t3;
                LDSM_X4(t0, t1, t2, t3, sB + sw_off(row, chunk));
                b[p * 2 + 0][0] = t0;  b[p * 2 + 0][1] = t1;
                b[p * 2 + 1][0] = t2;  b[p * 2 + 1][1] = t3;
            }
            #pragma unroll
            for (int i = 0; i < 4; i++)
                #pragma unroll
                for (int j = 0; j < 4; j++)
                    MMA_F16(acc[i][j], a[i], b[j]);
        }
        __syncthreads();
    }

    // epilogue: write split partial tile
    const int g  = lane >> 2;
    const int t4 = lane & 3;
    float* base = g_part[s];
    #pragma unroll
    for (int i = 0; i < 4; i++) {
        #pragma unroll
        for (int j = 0; j < 4; j++) {
            int row = m0 + wm + i * 16 + g;
            int col = n0 + wn + j * 8 + t4 * 2;
            *(float2*)&base[(size_t)row * NEURONS + col] =
                make_float2(acc[i][j][0], acc[i][j][1]);
            *(float2*)&base[(size_t)(row + 8) * NEURONS + col] =
                make_float2(acc[i][j][2], acc[i][j][3]);
        }
    }
}

// ---------------------------------------------------------------------------
// Kernel 3: sum split-K partials + bias (float4)
// ---------------------------------------------------------------------------
__global__ void __launch_bounds__(256) reduce_out(const float* __restrict__ W_b,
                                                  float* __restrict__ out) {
    int i4 = blockIdx.x * blockDim.x + threadIdx.x;
    int n4 = i4 & (NEURONS / 4 - 1);
    float4 a = ((const float4*)W_b)[n4];
    #pragma unroll
    for (int sp = 0; sp < SPLITS; sp++) {
        float4 p = *(const float4*)&g_part[sp][(size_t)i4 * 4];
        a.x += p.x; a.y += p.y; a.z += p.z; a.w += p.w;
    }
    ((float4*)out)[i4] = a;
}

// ---------------------------------------------------------------------------
// Entry point
// ---------------------------------------------------------------------------
extern "C" void kernel_launch(void* const* d_in, const int* in_sizes, int n_in,
                              void* d_out, int out_size) {
    const float* x   = (const float*)d_in[0];   // [512, 384, 13, 13]
    const float* W_s = (const float*)d_in[1];   // [512, 13, 13]
    const float* W_d = (const float*)d_in[2];   // [512, 384]
    const float* W_b = (const float*)d_in[3];   // [1, 512]
    float* out = (float*)d_out;                 // [512, 512]

    (void)cudaFuncSetAttribute(gemm_f16,
        cudaFuncAttributeMaxDynamicSharedMemorySize, SMEM_TOTAL);

    convert_x<<<(BATCH * K_TOTAL) / (256 * 8), 256>>>(x);

    dim3 pre_grid(NEURONS, 4);
    precompute_w<<<pre_grid, 256>>>(W_s, W_d);

    dim3 grid(NEURONS / BN, BATCH / BM, SPLITS);   // 4 x 4 x 18 = 288 CTAs
    gemm_f16<<<grid, 256, SMEM_TOTAL>>>();

    reduce_out<<<(BATCH * NEURONS) / (256 * 4), 256>>>(W_b, out);
}

// round 12
// speedup vs baseline: 2.6499x; 1.0708x over previous
#include <cuda_runtime.h>
#include <cuda_fp16.h>
#include <cstdint>

// ---------------------------------------------------------------------------
// Problem constants
// ---------------------------------------------------------------------------
#define NEURONS  512
#define CHANNELS 384
#define HWSZ     169
#define BATCH    512
#define K_TOTAL  (CHANNELS * HWSZ)      // 64896

// GEMM tiling: CTA 128x128, 4 warps of 64x64, k-tile = 64 halves (128 B row)
#define BM 128
#define BN 128
#define KH 64
#define TILES64 (K_TOTAL / KH)           // 1014
#define SPLITS 18                        // 6 splits of 57 tiles + 12 of 56
#define STAGES 3

#define A_BYTES (BM * 128)               // 16 KB (fp16)
#define B_BYTES (BN * 128)               // 16 KB
#define STAGE_BYTES (A_BYTES + B_BYTES)  // 32 KB
#define SMEM_TOTAL (STAGES * STAGE_BYTES)// 96 KB

// prep grid split
#define CONV_BLOCKS ((BATCH * K_TOTAL) / (256 * 8))   // 16224
#define PREP_BLOCKS (CONV_BLOCKS + NEURONS * 4)       // + 2048 = 18272

// Scratch (__device__ globals per allocation rules)
__device__ __half g_x[(size_t)BATCH * K_TOTAL];      // x converted to fp16
__device__ __half g_w[(size_t)NEURONS * K_TOTAL];    // rank-1 weights, fp16
__device__ float  g_part[SPLITS][BATCH * NEURONS];   // split-K partials

// ---------------------------------------------------------------------------
// Helpers (baseline PTX: sm_80-class; compute_103 target has no 'a' isa)
// ---------------------------------------------------------------------------
__device__ __forceinline__ uint32_t s2u(const void* p) {
    return (uint32_t)__cvta_generic_to_shared(p);
}

// Full SW128 swizzle: conflict-free for row fills and ldmatrix column reads.
__device__ __forceinline__ uint32_t sw_off(uint32_t row, uint32_t c16) {
    return row * 128u + ((c16 ^ (row & 7u)) << 4);
}

// pack two fp32 into one f16x2 reg: {hi, lo}
__device__ __forceinline__ uint32_t pack_f16(float hi, float lo) {
    uint32_t d;
    asm("cvt.rn.f16x2.f32 %0, %1, %2;" : "=r"(d) : "f"(hi), "f"(lo));
    return d;
}

#define CPA16(dst, src) \
    asm volatile("cp.async.cg.shared.global [%0], [%1], 16;" :: "r"(dst), "l"(src))
#define CP_COMMIT()  asm volatile("cp.async.commit_group;" ::: "memory")
#define CP_WAIT(n)   asm volatile("cp.async.wait_group %0;" :: "n"(n) : "memory")

#define LDSM_X4(r0, r1, r2, r3, a) \
    asm volatile("ldmatrix.sync.aligned.m8n8.x4.shared.b16 {%0,%1,%2,%3}, [%4];" \
                 : "=r"(r0), "=r"(r1), "=r"(r2), "=r"(r3) : "r"(a))

// fp16 MMA: m16n8k16, f32 accum
#define MMA_F16(c, a, b) \
    asm volatile("mma.sync.aligned.m16n8k16.row.col.f32.f16.f16.f32 " \
                 "{%0,%1,%2,%3},{%4,%5,%6,%7},{%8,%9},{%0,%1,%2,%3};" \
                 : "+f"((c)[0]), "+f"((c)[1]), "+f"((c)[2]), "+f"((c)[3]) \
                 : "r"((a)[0]), "r"((a)[1]), "r"((a)[2]), "r"((a)[3]), \
                   "r"((b)[0]), "r"((b)[1]))

// ---------------------------------------------------------------------------
// Kernel 1: merged prep.
//   Blocks [0, CONV_BLOCKS): convert x fp32 -> fp16 (8 elems/thread).
//   Blocks [CONV_BLOCKS, PREP_BLOCKS): g_w[n][k] = fp16(W_d[n,c]*W_s[n,hw]).
// ---------------------------------------------------------------------------
__global__ void __launch_bounds__(256) prep(const float* __restrict__ x,
                                            const float* __restrict__ W_s,
                                            const float* __restrict__ W_d) {
    if (blockIdx.x < CONV_BLOCKS) {
        const size_t idx = (size_t)blockIdx.x * 256 + threadIdx.x; // 8-elem slots
        const float4* src = (const float4*)x + idx * 2;
        float4 v0 = src[0];
        float4 v1 = src[1];
        uint4 o;
        o.x = pack_f16(v0.y, v0.x);
        o.y = pack_f16(v0.w, v0.z);
        o.z = pack_f16(v1.y, v1.x);
        o.w = pack_f16(v1.w, v1.z);
        ((uint4*)g_x)[idx] = o;
    } else {
        const int bid2 = blockIdx.x - CONV_BLOCKS;
        const int n = bid2 >> 2;
        const int q = bid2 & 3;
        __shared__ float ws[HWSZ];
        __shared__ float wd[CHANNELS];
        for (int i = threadIdx.x; i < HWSZ; i += 256)     ws[i] = W_s[n * HWSZ + i];
        for (int i = threadIdx.x; i < CHANNELS; i += 256) wd[i] = W_d[n * CHANNELS + i];
        __syncthreads();
        const int QK = K_TOTAL / 4;                      // 16224
        const int kbase = q * QK;
        uint4* dst = (uint4*)(g_w + (size_t)n * K_TOTAL + kbase);
        for (int v = threadIdx.x; v < QK / 8; v += 256) {
            int k = kbase + v * 8;
            float r[8];
            #pragma unroll
            for (int i = 0; i < 8; i++) {
                int ki = k + i;
                int c  = ki / HWSZ;                      // constant divisor -> mul-hi
                int hw = ki - c * HWSZ;
                r[i] = wd[c] * ws[hw];
            }
            uint4 o;
            o.x = pack_f16(r[1], r[0]);
            o.y = pack_f16(r[3], r[2]);
            o.z = pack_f16(r[5], r[4]);
            o.w = pack_f16(r[7], r[6]);
            dst[v] = o;
        }
    }
}

// ---------------------------------------------------------------------------
// Kernel 2: fp16 mma.sync split-K GEMM. 128 threads = 4 warps of 64x64.
// LDSM redundancy 2x on A and B.
// ---------------------------------------------------------------------------
__global__ void __launch_bounds__(128, 2) gemm_f16(void) {
    extern __shared__ char smem[];
    const uint32_t sbase = s2u(smem);

    const int tid  = threadIdx.x;
    const int wid  = tid >> 5;
    const int lane = tid & 31;
    const int n0 = blockIdx.x * BN;
    const int m0 = blockIdx.y * BM;
    const int s  = blockIdx.z;

    // uneven split-K over 1014 k64-tiles: first 6 splits get 57, rest 56
    const int NT  = 56 + (s < 6 ? 1 : 0);
    const int ts0 = 56 * s + (s < 6 ? s : 6);

    const __half* xbase = g_x + (size_t)m0 * K_TOTAL + (size_t)ts0 * KH;
    const __half* wbase = g_w + (size_t)n0 * K_TOTAL + (size_t)ts0 * KH;

    const int wm = (wid & 1) * 64;        // warp m offset
    const int wn = (wid >> 1) * 64;       // warp n offset
    const int sub = lane >> 3;            // 0..3
    const int r8  = lane & 7;

    float acc[4][8][4];                   // 4 m16 x 8 n8 fragments
    #pragma unroll
    for (int i = 0; i < 4; i++)
        #pragma unroll
        for (int j = 0; j < 8; j++)
            #pragma unroll
            for (int f = 0; f < 4; f++) acc[i][j][f] = 0.f;

    // stage fill: A 1024 + B 1024 16B chunks; 16 per thread
    auto fill = [&](int t) {
        const uint32_t sa = sbase + (t % STAGES) * STAGE_BYTES;
        const uint32_t sB = sa + A_BYTES;
        const __half* xs = xbase + (size_t)t * KH;
        const __half* wr = wbase + (size_t)t * KH;
        #pragma unroll
        for (int i = 0; i < 8; i++) {
            int slot = tid + i * 128;            // 0..1023
            uint32_t row = slot >> 3, c = slot & 7;
            uint32_t off = sw_off(row, c);
            CPA16(sa + off, xs + (size_t)row * K_TOTAL + c * 8);
            CPA16(sB + off, wr + (size_t)row * K_TOTAL + c * 8);
        }
        CP_COMMIT();
    };

    fill(0);
    fill(1);

    for (int t = 0; t < NT; t++) {
        CP_WAIT(1);
        __syncthreads();
        if (t + 2 < NT) fill(t + 2);

        const uint32_t sa = sbase + (t % STAGES) * STAGE_BYTES;
        const uint32_t sB = sa + A_BYTES;

        #pragma unroll
        for (int ks = 0; ks < 4; ks++) {         // four k16 steps per k64 tile
            // A: 4 m16k16 fragments (m-half = sub&1, k-chunk = sub>>1)
            uint32_t a[4][4];
            #pragma unroll
            for (int i = 0; i < 4; i++) {
                uint32_t row   = wm + i * 16 + (sub & 1) * 8 + r8;
                uint32_t chunk = ks * 2 + (sub >> 1);
                LDSM_X4(a[i][0], a[i][1], a[i][2], a[i][3],
                        sa + sw_off(row, chunk));
            }
            // B: 8 n8k16 fragments via 4 LDSM.x4 (n-half = sub>>1, k-chunk = sub&1)
            uint32_t b[8][2];
            #pragma unroll
            for (int p = 0; p < 4; p++) {
                uint32_t row   = wn + p * 16 + (sub >> 1) * 8 + r8;
                uint32_t chunk = ks * 2 + (sub & 1);
                uint32_t t0, t1, t2, t3;
                LDSM_X4(t0, t1, t2, t3, sB + sw_off(row, chunk));
                b[p * 2 + 0][0] = t0;  b[p * 2 + 0][1] = t1;
                b[p * 2 + 1][0] = t2;  b[p * 2 + 1][1] = t3;
            }
            #pragma unroll
            for (int i = 0; i < 4; i++)
                #pragma unroll
                for (int j = 0; j < 8; j++)
                    MMA_F16(acc[i][j], a[i], b[j]);
        }
        __syncthreads();
    }

    // epilogue: write split partial tile (64x64 per warp)
    const int g  = lane >> 2;
    const int t4 = lane & 3;
    float* base = g_part[s];
    #pragma unroll
    for (int i = 0; i < 4; i++) {
        #pragma unroll
        for (int j = 0; j < 8; j++) {
            int row = m0 + wm + i * 16 + g;
            int col = n0 + wn + j * 8 + t4 * 2;
            *(float2*)&base[(size_t)row * NEURONS + col] =
                make_float2(acc[i][j][0], acc[i][j][1]);
            *(float2*)&base[(size_t)(row + 8) * NEURONS + col] =
                make_float2(acc[i][j][2], acc[i][j][3]);
        }
    }
}

// ---------------------------------------------------------------------------
// Kernel 3: sum split-K partials + bias (float2, 512 blocks for occupancy)
// ---------------------------------------------------------------------------
__global__ void __launch_bounds__(256) reduce_out(const float* __restrict__ W_b,
                                                  float* __restrict__ out) {
    int i2 = blockIdx.x * blockDim.x + threadIdx.x;   // 131072 float2 slots
    int n2 = i2 & (NEURONS / 2 - 1);
    float2 a = ((const float2*)W_b)[n2];
    #pragma unroll
    for (int sp = 0; sp < SPLITS; sp++) {
        float2 p = *(const float2*)&g_part[sp][(size_t)i2 * 2];
        a.x += p.x; a.y += p.y;
    }
    ((float2*)out)[i2] = a;
}

// ---------------------------------------------------------------------------
// Entry point
// ---------------------------------------------------------------------------
extern "C" void kernel_launch(void* const* d_in, const int* in_sizes, int n_in,
                              void* d_out, int out_size) {
    const float* x   = (const float*)d_in[0];   // [512, 384, 13, 13]
    const float* W_s = (const float*)d_in[1];   // [512, 13, 13]
    const float* W_d = (const float*)d_in[2];   // [512, 384]
    const float* W_b = (const float*)d_in[3];   // [1, 512]
    float* out = (float*)d_out;                 // [512, 512]

    (void)cudaFuncSetAttribute(gemm_f16,
        cudaFuncAttributeMaxDynamicSharedMemorySize, SMEM_TOTAL);

    prep<<<PREP_BLOCKS, 256>>>(x, W_s, W_d);

    dim3 grid(NEURONS / BN, BATCH / BM, SPLITS);   // 4 x 4 x 18 = 288 CTAs
    gemm_f16<<<grid, 128, SMEM_TOTAL>>>();

    reduce_out<<<(BATCH * NEURONS) / (256 * 2), 256>>>(W_b, out);
}

// round 13
// speedup vs baseline: 2.7027x; 1.0199x over previous
#include <cuda_runtime.h>
#include <cuda_fp16.h>
#include <cstdint>

// ---------------------------------------------------------------------------
// Problem constants
// ---------------------------------------------------------------------------
#define NEURONS  512
#define CHANNELS 384
#define HWSZ     169
#define BATCH    512
#define K_TOTAL  (CHANNELS * HWSZ)      // 64896

// GEMM tiling: CTA 128x128, 4 warps of 64x64, k-tile = 64 halves (128 B row)
#define BM 128
#define BN 128
#define KH 64
#define TILES64 (K_TOTAL / KH)           // 1014
#define SPLITS 18                        // 6 splits of 57 tiles + 12 of 56
#define STAGES 3

#define A_BYTES (BM * 128)               // 16 KB (fp16)
#define B_BYTES (BN * 128)               // 16 KB
#define STAGE_BYTES (A_BYTES + B_BYTES)  // 32 KB
#define SMEM_TOTAL (STAGES * STAGE_BYTES)// 96 KB

// prep grid split: convert x (16 elems/thread) | build g_w | init out with bias
#define CONV_BLOCKS ((BATCH * K_TOTAL) / (256 * 16))          // 8112
#define W_BLOCKS    (NEURONS * 4)                             // 2048
#define OUT_BLOCKS  ((BATCH * NEURONS) / (256 * 4))           // 256
#define PREP_BLOCKS (CONV_BLOCKS + W_BLOCKS + OUT_BLOCKS)     // 10416

// Scratch (__device__ globals per allocation rules)
__device__ __half g_x[(size_t)BATCH * K_TOTAL];      // x converted to fp16
__device__ __half g_w[(size_t)NEURONS * K_TOTAL];    // rank-1 weights, fp16

// ---------------------------------------------------------------------------
// Helpers (baseline PTX: sm_80-class; compute_103 target has no 'a' isa)
// ---------------------------------------------------------------------------
__device__ __forceinline__ uint32_t s2u(const void* p) {
    return (uint32_t)__cvta_generic_to_shared(p);
}

// Full SW128 swizzle: conflict-free for row fills and ldmatrix column reads.
__device__ __forceinline__ uint32_t sw_off(uint32_t row, uint32_t c16) {
    return row * 128u + ((c16 ^ (row & 7u)) << 4);
}

// pack two fp32 into one f16x2 reg: {hi, lo}
__device__ __forceinline__ uint32_t pack_f16(float hi, float lo) {
    uint32_t d;
    asm("cvt.rn.f16x2.f32 %0, %1, %2;" : "=r"(d) : "f"(hi), "f"(lo));
    return d;
}

#define CPA16(dst, src) \
    asm volatile("cp.async.cg.shared.global [%0], [%1], 16;" :: "r"(dst), "l"(src))
#define CP_COMMIT()  asm volatile("cp.async.commit_group;" ::: "memory")
#define CP_WAIT(n)   asm volatile("cp.async.wait_group %0;" :: "n"(n) : "memory")

#define LDSM_X4(r0, r1, r2, r3, a) \
    asm volatile("ldmatrix.sync.aligned.m8n8.x4.shared.b16 {%0,%1,%2,%3}, [%4];" \
                 : "=r"(r0), "=r"(r1), "=r"(r2), "=r"(r3) : "r"(a))

// fp16 MMA: m16n8k16, f32 accum
#define MMA_F16(c, a, b) \
    asm volatile("mma.sync.aligned.m16n8k16.row.col.f32.f16.f16.f32 " \
                 "{%0,%1,%2,%3},{%4,%5,%6,%7},{%8,%9},{%0,%1,%2,%3};" \
                 : "+f"((c)[0]), "+f"((c)[1]), "+f"((c)[2]), "+f"((c)[3]) \
                 : "r"((a)[0]), "r"((a)[1]), "r"((a)[2]), "r"((a)[3]), \
                   "r"((b)[0]), "r"((b)[1]))

// fire-and-forget global fp32 reduction (REDG, sm_60+ baseline)
#define REDADD(p, v) \
    asm volatile("red.global.add.f32 [%0], %1;" :: "l"(p), "f"(v) : "memory")

// ---------------------------------------------------------------------------
// Kernel 1: merged prep.
//   [0, CONV_BLOCKS): convert x fp32 -> fp16, 16 elems/thread (MLP=4).
//   [CONV_BLOCKS, +W_BLOCKS): g_w[n][k] = fp16(W_d[n,c]*W_s[n,hw]).
//   [.., +OUT_BLOCKS): out[b,n] = W_b[n]  (bias init; GEMM atomically adds).
// ---------------------------------------------------------------------------
__global__ void __launch_bounds__(256) prep(const float* __restrict__ x,
                                            const float* __restrict__ W_s,
                                            const float* __restrict__ W_d,
                                            const float* __restrict__ W_b,
                                            float* __restrict__ out) {
    if (blockIdx.x < CONV_BLOCKS) {
        const size_t idx = (size_t)blockIdx.x * 256 + threadIdx.x; // 16-elem slot
        const float4* src = (const float4*)x + idx * 4;
        float4 v0 = src[0];
        float4 v1 = src[1];
        float4 v2 = src[2];
        float4 v3 = src[3];
        uint4 o0, o1;
        o0.x = pack_f16(v0.y, v0.x);  o0.y = pack_f16(v0.w, v0.z);
        o0.z = pack_f16(v1.y, v1.x);  o0.w = pack_f16(v1.w, v1.z);
        o1.x = pack_f16(v2.y, v2.x);  o1.y = pack_f16(v2.w, v2.z);
        o1.z = pack_f16(v3.y, v3.x);  o1.w = pack_f16(v3.w, v3.z);
        ((uint4*)g_x)[idx * 2]     = o0;
        ((uint4*)g_x)[idx * 2 + 1] = o1;
    } else if (blockIdx.x < CONV_BLOCKS + W_BLOCKS) {
        const int bid2 = blockIdx.x - CONV_BLOCKS;
        const int n = bid2 >> 2;
        const int q = bid2 & 3;
        __shared__ float ws[HWSZ];
        __shared__ float wd[CHANNELS];
        for (int i = threadIdx.x; i < HWSZ; i += 256)     ws[i] = W_s[n * HWSZ + i];
        for (int i = threadIdx.x; i < CHANNELS; i += 256) wd[i] = W_d[n * CHANNELS + i];
        __syncthreads();
        const int QK = K_TOTAL / 4;                      // 16224
        const int kbase = q * QK;
        uint4* dst = (uint4*)(g_w + (size_t)n * K_TOTAL + kbase);
        for (int v = threadIdx.x; v < QK / 8; v += 256) {
            int k = kbase + v * 8;
            float r[8];
            #pragma unroll
            for (int i = 0; i < 8; i++) {
                int ki = k + i;
                int c  = ki / HWSZ;                      // constant divisor -> mul-hi
                int hw = ki - c * HWSZ;
                r[i] = wd[c] * ws[hw];
            }
            uint4 o;
            o.x = pack_f16(r[1], r[0]);
            o.y = pack_f16(r[3], r[2]);
            o.z = pack_f16(r[5], r[4]);
            o.w = pack_f16(r[7], r[6]);
            dst[v] = o;
        }
    } else {
        const int i4 = (blockIdx.x - CONV_BLOCKS - W_BLOCKS) * 256 + threadIdx.x;
        const int n4 = i4 & (NEURONS / 4 - 1);
        ((float4*)out)[i4] = ((const float4*)W_b)[n4];
    }
}

// ---------------------------------------------------------------------------
// Kernel 2: fp16 mma.sync split-K GEMM. 128 threads = 4 warps of 64x64.
// Epilogue: red.global.add.f32 directly into out (bias pre-initialized).
// ---------------------------------------------------------------------------
__global__ void __launch_bounds__(128, 2) gemm_f16(float* __restrict__ out) {
    extern __shared__ char smem[];
    const uint32_t sbase = s2u(smem);

    const int tid  = threadIdx.x;
    const int wid  = tid >> 5;
    const int lane = tid & 31;
    const int n0 = blockIdx.x * BN;
    const int m0 = blockIdx.y * BM;
    const int s  = blockIdx.z;

    // uneven split-K over 1014 k64-tiles: first 6 splits get 57, rest 56
    const int NT  = 56 + (s < 6 ? 1 : 0);
    const int ts0 = 56 * s + (s < 6 ? s : 6);

    const __half* xbase = g_x + (size_t)m0 * K_TOTAL + (size_t)ts0 * KH;
    const __half* wbase = g_w + (size_t)n0 * K_TOTAL + (size_t)ts0 * KH;

    const int wm = (wid & 1) * 64;        // warp m offset
    const int wn = (wid >> 1) * 64;       // warp n offset
    const int sub = lane >> 3;            // 0..3
    const int r8  = lane & 7;

    float acc[4][8][4];                   // 4 m16 x 8 n8 fragments
    #pragma unroll
    for (int i = 0; i < 4; i++)
        #pragma unroll
        for (int j = 0; j < 8; j++)
            #pragma unroll
            for (int f = 0; f < 4; f++) acc[i][j][f] = 0.f;

    // stage fill: A 1024 + B 1024 16B chunks; 16 per thread
    auto fill = [&](int t) {
        const uint32_t sa = sbase + (t % STAGES) * STAGE_BYTES;
        const uint32_t sB = sa + A_BYTES;
        const __half* xs = xbase + (size_t)t * KH;
        const __half* wr = wbase + (size_t)t * KH;
        #pragma unroll
        for (int i = 0; i < 8; i++) {
            int slot = tid + i * 128;            // 0..1023
            uint32_t row = slot >> 3, c = slot & 7;
            uint32_t off = sw_off(row, c);
            CPA16(sa + off, xs + (size_t)row * K_TOTAL + c * 8);
            CPA16(sB + off, wr + (size_t)row * K_TOTAL + c * 8);
        }
        CP_COMMIT();
    };

    fill(0);
    fill(1);

    for (int t = 0; t < NT; t++) {
        CP_WAIT(1);
        __syncthreads();
        if (t + 2 < NT) fill(t + 2);

        const uint32_t sa = sbase + (t % STAGES) * STAGE_BYTES;
        const uint32_t sB = sa + A_BYTES;

        #pragma unroll
        for (int ks = 0; ks < 4; ks++) {         // four k16 steps per k64 tile
            // A: 4 m16k16 fragments (m-half = sub&1, k-chunk = sub>>1)
            uint32_t a[4][4];
            #pragma unroll
            for (int i = 0; i < 4; i++) {
                uint32_t row   = wm + i * 16 + (sub & 1) * 8 + r8;
                uint32_t chunk = ks * 2 + (sub >> 1);
                LDSM_X4(a[i][0], a[i][1], a[i][2], a[i][3],
                        sa + sw_off(row, chunk));
            }
            // B: 8 n8k16 fragments via 4 LDSM.x4 (n-half = sub>>1, k-chunk = sub&1)
            uint32_t b[8][2];
            #pragma unroll
            for (int p = 0; p < 4; p++) {
                uint32_t row   = wn + p * 16 + (sub >> 1) * 8 + r8;
                uint32_t chunk = ks * 2 + (sub & 1);
                uint32_t t0, t1, t2, t3;
                LDSM_X4(t0, t1, t2, t3, sB + sw_off(row, chunk));
                b[p * 2 + 0][0] = t0;  b[p * 2 + 0][1] = t1;
                b[p * 2 + 1][0] = t2;  b[p * 2 + 1][1] = t3;
            }
            #pragma unroll
            for (int i = 0; i < 4; i++)
                #pragma unroll
                for (int j = 0; j < 8; j++)
                    MMA_F16(acc[i][j], a[i], b[j]);
        }
        __syncthreads();
    }

    // epilogue: atomically accumulate the 64x64 warp tile into out
    const int g  = lane >> 2;
    const int t4 = lane & 3;
    #pragma unroll
    for (int i = 0; i < 4; i++) {
        #pragma unroll
        for (int j = 0; j < 8; j++) {
            int row = m0 + wm + i * 16 + g;
            int col = n0 + wn + j * 8 + t4 * 2;
            float* p0 = out + (size_t)row * NEURONS + col;
            float* p1 = out + (size_t)(row + 8) * NEURONS + col;
            REDADD(p0,     acc[i][j][0]);
            REDADD(p0 + 1, acc[i][j][1]);
            REDADD(p1,     acc[i][j][2]);
            REDADD(p1 + 1, acc[i][j][3]);
        }
    }
}

// ---------------------------------------------------------------------------
// Entry point
// ---------------------------------------------------------------------------
extern "C" void kernel_launch(void* const* d_in, const int* in_sizes, int n_in,
                              void* d_out, int out_size) {
    const float* x   = (const float*)d_in[0];   // [512, 384, 13, 13]
    const float* W_s = (const float*)d_in[1];   // [512, 13, 13]
    const float* W_d = (const float*)d_in[2];   // [512, 384]
    const float* W_b = (const float*)d_in[3];   // [1, 512]
    float* out = (float*)d_out;                 // [512, 512]

    (void)cudaFuncSetAttribute(gemm_f16,
        cudaFuncAttributeMaxDynamicSharedMemorySize, SMEM_TOTAL);

    prep<<<PREP_BLOCKS, 256>>>(x, W_s, W_d, W_b, out);

    dim3 grid(NEURONS / BN, BATCH / BM, SPLITS);   // 4 x 4 x 18 = 288 CTAs
    gemm_f16<<<grid, 128, SMEM_TOTAL>>>(out);
}